// round 9
// baseline (speedup 1.0000x reference)
#include <cuda_runtime.h>
#include <cuda_bf16.h>

// KANStressPredictor: elementwise map over [B, T, 3] f32 strain.
// Group math (s0,s1,s2):
//   mean = s0+s1+1 ;  rad = sqrt((s0-s1)^2 + s2^2)
//   lam0 = mean-rad, lam1 = mean+rad    [eigenvalues of C = 2E+I]
//   lg_i = log2(lam_i) ;  L = lg0+lg1 = log2(det C)
//   out_i = exp2( ki0*0.5*lg_i - ki0*L/6 ) ;  out_2 = 0.5*ln2*ki1 * L
//
// R9: R8 float2 scheme + 2 independent window-pairs per thread (pair t and
// pair t+half). R8 profile had nothing saturated (DRAM 64/L1 49/issue 43):
// per-warp latency exposure with MLP=2. Front-batching 4 independent
// LDG.128 doubles in-flight bytes per warp; halves warp count.

#define LN2_F 0.6931471805599453f

__device__ __forceinline__ float ex2_approx(float x) {
    float r;
    asm("ex2.approx.ftz.f32 %0, %1;" : "=f"(r) : "f"(x));
    return r;
}

__device__ __forceinline__ void kan_group(float s0, float s1, float s2,
                                          float ki0h, float ki0_6, float k1s,
                                          float& o0, float& o1, float& o2) {
    float mean = s0 + s1 + 1.0f;
    float diff = s0 - s1;
    float rad  = __fsqrt_rn(fmaf(diff, diff, s2 * s2));

    float lam0 = mean - rad;                   // rad < 0.3*mean: no cancellation
    float lam1 = mean + rad;
    float lg0  = __log2f(lam0);
    float lg1  = __log2f(lam1);
    float L    = lg0 + lg1;                    // log2(det)

    float base = ki0_6 * L;
    o0 = ex2_approx(fmaf(ki0h, lg0, -base));
    o1 = ex2_approx(fmaf(ki0h, lg1, -base));
    o2 = k1s * L;
}

// Routing for one window-pair p: floats 6p..6p+5 live in f4 slots s=(3p)>>1,
// s+1 at parity offset. Outputs in natural order -> 3 STG.64.
__device__ __forceinline__ void window_pair(const float4& L0, const float4& L1, bool odd,
                                            float ki0h, float ki0_6, float k1s,
                                            float2& w0, float2& w1, float2& w2) {
    float a0 = odd ? L0.z : L0.x;
    float a1 = odd ? L0.w : L0.y;
    float a2 = odd ? L1.x : L0.z;
    float b0 = odd ? L1.y : L0.w;
    float b1 = odd ? L1.z : L1.x;
    float b2 = odd ? L1.w : L1.y;

    float A0, A1, A2, B0, B1, B2;
    kan_group(a0, a1, a2, ki0h, ki0_6, k1s, A0, A1, A2);
    kan_group(b0, b1, b2, ki0h, ki0_6, k1s, B0, B1, B2);

    w0 = make_float2(A0, A1);
    w1 = make_float2(A2, B0);
    w2 = make_float2(B1, B2);
}

__global__ void __launch_bounds__(256)
kan_stress_f2x2_kernel(const float4* __restrict__ in, float2* __restrict__ out2,
                       const float* __restrict__ ki0p, const float* __restrict__ ki1p,
                       int half) {
    int t = blockIdx.x * blockDim.x + threadIdx.x;
    if (t >= half) return;

    int p0 = t;
    int p1 = t + half;
    int s0i = (3 * p0) >> 1;
    int s1i = (3 * p1) >> 1;
    bool odd0 = (p0 & 1) != 0;
    bool odd1 = (p1 & 1) != 0;

    // 4 independent LDG.128 front-batched (MLP_p1 = 4)
    float4 P0a = in[s0i];
    float4 P0b = in[s0i + 1];
    float4 P1a = in[s1i];
    float4 P1b = in[s1i + 1];

    float ki0 = __ldg(ki0p);
    float ki1 = __ldg(ki1p);
    float ki0h  = 0.5f * ki0;
    float ki0_6 = ki0 * (1.0f / 6.0f);
    float k1s   = 0.5f * LN2_F * ki1;

    float2 a0, a1, a2, b0, b1, b2;
    window_pair(P0a, P0b, odd0, ki0h, ki0_6, k1s, a0, a1, a2);
    window_pair(P1a, P1b, odd1, ki0h, ki0_6, k1s, b0, b1, b2);

    long long o0 = 3LL * p0;
    out2[o0 + 0] = a0;
    out2[o0 + 1] = a1;
    out2[o0 + 2] = a2;

    long long o1 = 3LL * p1;
    out2[o1 + 0] = b0;
    out2[o1 + 1] = b1;
    out2[o1 + 2] = b2;
}

// Scalar fallback for groups not covered by the main kernel (defensive;
// unused for the benchmarked 4096x2048x3 shape which divides exactly).
__global__ void kan_stress_tail_kernel(const float* __restrict__ in, float* __restrict__ out,
                                       const float* __restrict__ ki0p, const float* __restrict__ ki1p,
                                       long long g0, long long n_groups) {
    long long g = g0 + blockIdx.x * (long long)blockDim.x + threadIdx.x;
    if (g >= n_groups) return;

    float ki0 = __ldg(ki0p);
    float ki1 = __ldg(ki1p);
    float ki0h  = 0.5f * ki0;
    float ki0_6 = ki0 * (1.0f / 6.0f);
    float k1s   = 0.5f * LN2_F * ki1;

    float s0 = in[3 * g + 0];
    float s1 = in[3 * g + 1];
    float s2 = in[3 * g + 2];
    float o0, o1, o2;
    kan_group(s0, s1, s2, ki0h, ki0_6, k1s, o0, o1, o2);
    out[3 * g + 0] = o0;
    out[3 * g + 1] = o1;
    out[3 * g + 2] = o2;
}

extern "C" void kernel_launch(void* const* d_in, const int* in_sizes, int n_in,
                              void* d_out, int out_size) {
    const float* strain = (const float*)d_in[0];
    const float* ki0    = (const float*)d_in[1];
    const float* ki1    = (const float*)d_in[2];
    float* out          = (float*)d_out;

    long long total_floats = in_sizes[0];     // B*T*3
    long long n_groups = total_floats / 3;

    // number of window-pairs with in-bounds f4 reads (4*((3p)>>1)+7 < total)
    long long np = n_groups / 2;
    while (np > 0) {
        long long last_s = (3 * (np - 1)) >> 1;
        if (4 * last_s + 7 < total_floats) break;
        np--;
    }
    np &= ~1LL;                               // even: two pairs per thread
    long long half = np / 2;                  // bench: 25165824 -> half=2097152

    if (half > 0) {
        int block = 256;
        int grid = (int)((half + block - 1) / block);
        kan_stress_f2x2_kernel<<<grid, block>>>(
            (const float4*)strain, (float2*)out, ki0, ki1, (int)half);
    }

    long long g0 = 2 * np;                    // first uncovered group
    if (g0 < n_groups) {
        long long rem = n_groups - g0;
        int block = 128;
        int grid = (int)((rem + block - 1) / block);
        kan_stress_tail_kernel<<<grid, block>>>(strain, out, ki0, ki1, g0, n_groups);
    }
}